// round 14
// baseline (speedup 1.0000x reference)
#include <cuda_runtime.h>
#include <math.h>

// B=16, S=128, N=64, E=DK=H=128, L=32

__device__ float g_Xg[2*16*128*512];
__device__ float g_Xl[2*16*128*128];
__device__ float g_Wg[2*16*64*384];
__device__ float g_feats[16*128*256];
__device__ float g_logits[16*128*32];
__device__ float g_res[16];
__device__ float g_hh[32][129*128];   // full h history per (dir,b)

__device__ __forceinline__ float sigm(float x) { return 1.f / (1.f + expf(-x)); }

__device__ __forceinline__ unsigned smem_u32(const void* p) {
    unsigned a;
    asm("{ .reg .u64 t; cvta.to.shared.u64 t, %1; cvt.u32.u64 %0, t; }" : "=r"(a) : "l"(p));
    return a;
}
__device__ __forceinline__ void st_peer_f32(unsigned a, int p, float v) {
    unsigned r;
    asm volatile("mapa.shared::cluster.u32 %0, %1, %2;" : "=r"(r) : "r"(a), "r"(p));
    asm volatile("st.shared::cluster.f32 [%0], %1;" :: "r"(r), "f"(v) : "memory");
}
__device__ __forceinline__ void mbar_init(unsigned a, unsigned c) {
    asm volatile("mbarrier.init.shared.b64 [%0], %1;" :: "r"(a), "r"(c) : "memory");
}
__device__ __forceinline__ void mbar_arrive_self(unsigned a) {
    asm volatile("mbarrier.arrive.release.cluster.shared::cta.b64 _, [%0];" :: "r"(a) : "memory");
}
__device__ __forceinline__ void mbar_arrive_peer(unsigned a, int p) {
    unsigned r;
    asm volatile("mapa.shared::cluster.u32 %0, %1, %2;" : "=r"(r) : "r"(a), "r"(p));
    asm volatile("mbarrier.arrive.release.cluster.shared::cluster.b64 _, [%0];" :: "r"(r) : "memory");
}
__device__ __forceinline__ void mbar_wait(unsigned a, unsigned parity) {
    asm volatile("{\n\t.reg .pred P;\n"
        "WL%=:\n\tmbarrier.try_wait.parity.acquire.cluster.shared::cta.b64 P, [%0], %1, 0x989680;\n"
        "\t@P bra WD%=;\n\tbra WL%=;\nWD%=:\n\t}" :: "r"(a), "r"(parity) : "memory");
}
__device__ __forceinline__ void cluster_sync_() {
    asm volatile("barrier.cluster.arrive.aligned;" ::: "memory");
    asm volatile("barrier.cluster.wait.aligned;" ::: "memory");
}

// ---------------- precompute GEMMs with embedding gather ----------------
__global__ void gemm_gather_kernel(int mode,
    const int* __restrict__ char_ids, const int* __restrict__ kb_ids,
    const float* __restrict__ char_emb, const float* __restrict__ kb_emb,
    const float* __restrict__ Wf, const float* __restrict__ Wr,
    const float* __restrict__ bf, const float* __restrict__ br,
    int C, int rows_per_dir)
{
    __shared__ float As[64 * 128];
    __shared__ float Wsm[32 * 64];
    __shared__ int ids[64];
    int tid = threadIdx.x;
    int c0 = blockIdx.x * 64;
    int r0 = blockIdx.y * 64;
    int dir = (r0 >= rows_per_dir) ? 1 : 0;
    float* out = (mode == 0) ? g_Xg : (mode == 1) ? g_Xl : g_Wg;
    const float* emb = (mode == 2) ? kb_emb : char_emb;
    if (tid < 64) {
        int r = r0 + tid, id;
        if (mode < 2) {
            int t = r & 127, b = (r >> 7) & 15;
            int pos = dir ? (127 - t) : t;
            id = char_ids[b * 128 + pos];
        } else {
            int w = r & 63, b = (r >> 6) & 15;
            id = kb_ids[b * 64 + w];
        }
        ids[tid] = id;
    }
    __syncthreads();
    for (int i = tid; i < 64 * 32; i += 256) {
        int row = i >> 5, q = i & 31;
        float4 v = reinterpret_cast<const float4*>(emb + (size_t)ids[row] * 128)[q];
        reinterpret_cast<float4*>(As + row * 128)[q] = v;
    }
    const float* W = dir ? Wr : Wf;
    const float* bias = dir ? br : bf;
    int tx = tid & 15, ty = tid >> 4;
    float acc[4][4] = {};
    for (int kc = 0; kc < 4; ++kc) {
        __syncthreads();
        for (int i = tid; i < 2048; i += 256) {
            int kk = i >> 6, cc = i & 63;
            Wsm[i] = W[(size_t)(kc * 32 + kk) * C + c0 + cc];
        }
        __syncthreads();
        #pragma unroll 8
        for (int kk = 0; kk < 32; ++kk) {
            float a0 = As[(ty*4+0)*128 + kc*32+kk], a1 = As[(ty*4+1)*128 + kc*32+kk];
            float a2 = As[(ty*4+2)*128 + kc*32+kk], a3 = As[(ty*4+3)*128 + kc*32+kk];
            float w0 = Wsm[kk*64+tx*4], w1 = Wsm[kk*64+tx*4+1];
            float w2 = Wsm[kk*64+tx*4+2], w3 = Wsm[kk*64+tx*4+3];
            acc[0][0]=fmaf(a0,w0,acc[0][0]); acc[0][1]=fmaf(a0,w1,acc[0][1]);
            acc[0][2]=fmaf(a0,w2,acc[0][2]); acc[0][3]=fmaf(a0,w3,acc[0][3]);
            acc[1][0]=fmaf(a1,w0,acc[1][0]); acc[1][1]=fmaf(a1,w1,acc[1][1]);
            acc[1][2]=fmaf(a1,w2,acc[1][2]); acc[1][3]=fmaf(a1,w3,acc[1][3]);
            acc[2][0]=fmaf(a2,w0,acc[2][0]); acc[2][1]=fmaf(a2,w1,acc[2][1]);
            acc[2][2]=fmaf(a2,w2,acc[2][2]); acc[2][3]=fmaf(a2,w3,acc[2][3]);
            acc[3][0]=fmaf(a3,w0,acc[3][0]); acc[3][1]=fmaf(a3,w1,acc[3][1]);
            acc[3][2]=fmaf(a3,w2,acc[3][2]); acc[3][3]=fmaf(a3,w3,acc[3][3]);
        }
    }
    #pragma unroll
    for (int i = 0; i < 4; ++i) {
        int r = r0 + ty * 4 + i;
        #pragma unroll
        for (int j = 0; j < 4; ++j)
            out[(size_t)r * C + c0 + tx * 4 + j] = acc[i][j] + bias[c0 + tx * 4 + j];
    }
}

// ---------------- lattice: 4-CTA cluster serves 2 same-dir sequences ----------------
// smem float offsets:
#define SM_WS   0        // Wch perm slice [k][cl] 16384
#define SM_WW   16384    // Wwh perm slice 12288
#define SM_WL   28672    // Wlc slice 4096
#define SM_HB   32768    // hbuf [2 par][2 seq][128] 512
#define SM_CH   33280    // ch [2 seq][129][32] 8256
#define SM_PART 41536    // [2][256]
#define SM_WVS  42048    // [2][96] pad 192
#define SM_CWB  42240    // [2 slot][2 ev][128] 512
#define SM_HBS  42752    // [2][128] 256
#define SM_EWA  43008    // 64
#define SM_EWC  43072    // 64
#define SM_XLS  43136    // 64
#define LAT_FLOATS 43200 // 172800 B

__global__ void __cluster_dims__(4, 1, 1) __launch_bounds__(256, 1)
lattice_kernel(
    const int* __restrict__ word_begin, const int* __restrict__ word_len,
    const int* __restrict__ seq_len,
    const float* __restrict__ f_Wch, const float* __restrict__ f_Wwh, const float* __restrict__ f_Wlc,
    const float* __restrict__ r_Wch, const float* __restrict__ r_Wwh, const float* __restrict__ r_Wlc)
{
    extern __shared__ float sm[];
    float* Ws   = sm + SM_WS;
    float* Ww   = sm + SM_WW;
    float* Wl   = sm + SM_WL;
    float* hbuf = sm + SM_HB;
    float* ch   = sm + SM_CH;
    float* part = sm + SM_PART;
    float* wvs  = sm + SM_WVS;
    float* cwb  = sm + SM_CWB;
    float* hbs  = sm + SM_HBS;
    float* ewa  = sm + SM_EWA;
    float* ewca = sm + SM_EWC;
    float* xls  = sm + SM_XLS;
    __shared__ int s_wbeg[2][64], s_wend[2][64], s_evt[128];
    __shared__ unsigned s_mask[4];
    __shared__ __align__(8) unsigned long long s_barh[2], s_barw[2];

    int tid = threadIdx.x, cta = blockIdx.x;
    int pid = cta >> 2, rank = cta & 3;
    int dir = pid >> 3, b0 = (pid & 7) * 2;
    const float* Wch = dir ? r_Wch : f_Wch;
    const float* Wwh = dir ? r_Wwh : f_Wwh;
    const float* Wlc = dir ? r_Wlc : f_Wlc;
    int sid0 = dir * 16 + b0;
    const float* Xg = g_Xg + (size_t)sid0 * 65536;
    const float* Xl = g_Xl + (size_t)sid0 * 16384;
    const float* Wg = g_Wg + (size_t)sid0 * 24576;
    int Lb0 = seq_len[b0], Lb1 = seq_len[b0 + 1];
    int cbase = rank * 32;

    for (int i = tid; i < 16384; i += 256) {
        int k = i >> 7, cl = i & 127;
        Ws[i] = Wch[(size_t)k * 512 + (cl >> 5) * 128 + cbase + (cl & 31)];
    }
    for (int i = tid; i < 12288; i += 256) {
        int k = i / 96, cl = i % 96;
        Ww[i] = Wwh[(size_t)k * 384 + (cl >> 5) * 128 + cbase + (cl & 31)];
    }
    for (int i = tid; i < 4096; i += 256) {
        int k = i >> 5, j = i & 31;
        Wl[i] = Wlc[(size_t)k * 128 + cbase + j];
    }
    { hbuf[tid] = 0.f; hbuf[256 + tid] = 0.f; }
    if (tid < 64) {
        int s = tid >> 5, j = tid & 31;
        ch[(s * 129) * 32 + j] = 0.f;
        g_hh[sid0 + s][cbase + j] = 0.f;
    }
    if (tid == 0) {
        mbar_init(smem_u32(&s_barh[0]), 8); mbar_init(smem_u32(&s_barh[1]), 8);
        mbar_init(smem_u32(&s_barw[0]), 8); mbar_init(smem_u32(&s_barw[1]), 8);
    }
    if (tid < 128) {
        int s = tid >> 6, w = tid & 63;
        int bg = word_begin[(b0 + s) * 64 + w];
        int ln = word_len[(b0 + s) * 64 + w];
        int e = min(bg + ln, 127);
        int Lb = s ? Lb1 : Lb0;
        int be, en;
        if (dir == 0) { be = bg; en = e; } else { be = 127 - e; en = 127 - bg; }
        s_wbeg[s][w] = be;
        s_wend[s][w] = (e < Lb) ? en : -1;
    }
    __syncthreads();
    cluster_sync_();

    unsigned bh0 = smem_u32(&s_barh[0]);
    unsigned bw0 = smem_u32(&s_barw[0]);
    int ecnt = 0;
    int kg = tid >> 7, cl = tid & 127;
    int ps = tid >> 5, pj = tid & 31;

    for (int t = 0; t < 128; ++t) {
        int par = t & 1;
        float xg0 = 0.f, xg1 = 0.f, xg2 = 0.f, xg3 = 0.f;
        if (tid < 64) {
            const float* xp = Xg + (size_t)ps * 65536 + (size_t)t * 512 + cbase + pj;
            xg0 = xp[0]; xg1 = xp[128]; xg2 = xp[256]; xg3 = xp[384];
        }
        if (tid < 128) {
            int s = tid >> 6, w = tid & 63;
            unsigned m = __ballot_sync(0xffffffffu, s_wend[s][w] == t);
            if ((tid & 31) == 0) s_mask[tid >> 5] = m;
        }
        // ---- fused gate GEMV: weights read once, FMA for both seqs ----
        {
            const float* wp = Ws + kg * 8192 + cl;
            const float4* ha = reinterpret_cast<const float4*>(hbuf + par * 256) + kg * 16;
            const float4* hb = reinterpret_cast<const float4*>(hbuf + par * 256 + 128) + kg * 16;
            float a0 = 0.f, a1 = 0.f, c0_ = 0.f, c1_ = 0.f;
            #pragma unroll
            for (int q = 0; q < 16; ++q) {
                float4 av = ha[q], bv = hb[q];
                const float* w = wp + q * 512;
                float w0 = w[0], w1 = w[128], w2 = w[256], w3 = w[384];
                a0 = fmaf(av.x, w0, a0); c0_ = fmaf(bv.x, w0, c0_);
                a1 = fmaf(av.y, w1, a1); c1_ = fmaf(bv.y, w1, c1_);
                a0 = fmaf(av.z, w2, a0); c0_ = fmaf(bv.z, w2, c0_);
                a1 = fmaf(av.w, w3, a1); c1_ = fmaf(bv.w, w3, c1_);
            }
            part[tid] = a0 + a1;
            part[256 + tid] = c0_ + c1_;
        }
        __syncthreads();
        unsigned m0 = s_mask[0], m1 = s_mask[1], m2 = s_mask[2], m3 = s_mask[3];
        int cnt0 = __popc(m0) + __popc(m1);
        int nev = cnt0 + __popc(m2) + __popc(m3);
        float gi = 0.f, gf = 0.f, go = 0.f, gg_ = 0.f;
        if (tid < 64) {
            const float* P = part + ps * 256;
            gi  = P[pj]       + P[128 + pj] + xg0;
            gf  = P[32 + pj]  + P[160 + pj] + xg1;
            go  = P[64 + pj]  + P[192 + pj] + xg2;
            gg_ = P[96 + pj]  + P[224 + pj] + xg3;
        }
        if (nev) {
            if (tid < 128) {
                int s = tid >> 6, w = tid & 63;
                if (s_wend[s][w] == t) {
                    int idx;
                    if (s == 0) idx = (w < 32) ? __popc(m0 & ((1u << w) - 1u))
                                               : __popc(m0) + __popc(m1 & ((1u << (w - 32)) - 1u));
                    else idx = cnt0 + ((w < 32) ? __popc(m2 & ((1u << w) - 1u))
                                                : __popc(m2) + __popc(m3 & ((1u << (w - 32)) - 1u)));
                    s_evt[idx] = (s << 8) | w;
                }
            }
            if (tid < 64) { ewa[tid] = 0.f; ewca[tid] = 0.f; }
            __syncthreads();
            for (int r = 0; r < nev; r += 2, ++ecnt) {
                int ev0 = s_evt[r];
                int has1 = (r + 1 < nev);
                int ev1 = has1 ? s_evt[r + 1] : ev0;
                int se0 = ev0 >> 8, w0_ = ev0 & 255;
                int se1 = ev1 >> 8, w1_ = ev1 & 255;
                int bg0 = s_wbeg[se0][w0_], bg1 = s_wbeg[se1][w1_];
                int slot = ecnt & 1;
                // prefetch hb (global), Wg, Xl
                if (tid < 128) hbs[tid] = g_hh[sid0 + se0][bg0 * 128 + tid];
                else           hbs[tid] = g_hh[sid0 + se1][bg1 * 128 + (tid - 128)];
                float wgp = 0.f;
                if (tid < 192) {
                    int e = (tid >= 96), c3 = e ? tid - 96 : tid;
                    int se = e ? se1 : se0, wd = e ? w1_ : w0_;
                    wgp = Wg[(size_t)se * 24576 + (size_t)wd * 384 + (c3 >> 5) * 128 + cbase + (c3 & 31)];
                }
                if (tid < 64) {
                    int e = tid >> 5, j = tid & 31;
                    int se = e ? se1 : se0;
                    xls[tid] = Xl[(size_t)se * 16384 + (size_t)t * 128 + cbase + j];
                }
                __syncthreads();
                // fused Ww GEMV (both events share weight reads)
                if (tid < 192) {
                    int kg2 = (tid >= 96), c3 = kg2 ? tid - 96 : tid;
                    const float* wp = Ww + kg2 * 6144 + c3;
                    const float* h0 = hbs + kg2 * 64;
                    const float* h1 = hbs + 128 + kg2 * 64;
                    float a0 = 0.f, a1 = 0.f;
                    #pragma unroll 8
                    for (int k = 0; k < 64; ++k) {
                        float wv_ = wp[k * 96];
                        a0 = fmaf(h0[k], wv_, a0);
                        a1 = fmaf(h1[k], wv_, a1);
                    }
                    part[tid] = a0;
                    part[256 + tid] = a1;
                }
                __syncthreads();
                if (tid < 192) {
                    int e = (tid >= 96), c3 = e ? tid - 96 : tid;
                    const float* P = part + e * 256;
                    wvs[e * 96 + c3] = P[c3] + P[96 + c3] + wgp;
                }
                __syncthreads();
                unsigned bwa = bw0 + (unsigned)slot * 8;
                if (tid < 64) {
                    int e = tid >> 5, j = tid & 31;
                    int se = e ? se1 : se0, bg = e ? bg1 : bg0;
                    float wi = sigm(wvs[e * 96 + j]);
                    float wf = sigm(wvs[e * 96 + 32 + j]);
                    float wg2 = tanhf(wvs[e * 96 + 64 + j]);
                    float cwv = wf * ch[(se * 129 + bg) * 32 + j] + wi * wg2;
                    int off = slot * 256 + e * 128 + cbase + j;
                    unsigned la = smem_u32(&cwb[off]);
                    cwb[off] = cwv;
                    #pragma unroll
                    for (int p = 0; p < 4; ++p) if (p != rank) st_peer_f32(la, p, cwv);
                    __syncwarp();
                    if ((tid & 31) == 0) {
                        mbar_arrive_self(bwa);
                        #pragma unroll
                        for (int p = 0; p < 4; ++p) if (p != rank) mbar_arrive_peer(bwa, p);
                    }
                }
                mbar_wait(bwa, (unsigned)((ecnt >> 1) & 1));
                // fused lg GEMV: 128 threads per event
                {
                    int e = tid >> 7, t2 = tid & 127, kg3 = t2 >> 5, j = t2 & 31;
                    const float* wp = Wl + kg3 * 1024 + j;
                    const float* cf = cwb + slot * 256 + e * 128 + kg3 * 32;
                    float a0 = 0.f;
                    #pragma unroll
                    for (int q = 0; q < 32; ++q) a0 = fmaf(cf[q], wp[q * 32], a0);
                    part[e * 256 + t2] = a0;
                }
                __syncthreads();
                if (tid < 32) {
                    int en = has1 ? 2 : 1;
                    for (int e = 0; e < en; ++e) {
                        int se = e ? se1 : se0;
                        const float* P = part + e * 256;
                        float s = P[tid] + P[32 + tid] + P[64 + tid] + P[96 + tid] + xls[e * 32 + tid];
                        float ev = expf(sigm(s));
                        ewa[se * 32 + tid] += ev;
                        ewca[se * 32 + tid] += ev * cwb[slot * 256 + e * 128 + cbase + tid];
                    }
                }
                __syncthreads();
            }
        }
        // ---- pointwise (2 warps, one per seq) + h push ----
        unsigned bha = bh0 + (unsigned)par * 8;
        if (tid < 64) {
            int wc = ps ? (__popc(m2) + __popc(m3)) : cnt0;
            float i_ = sigm(gi), f_ = sigm(gf), o_ = sigm(go), g2 = tanhf(gg_);
            float cp = ch[(ps * 129 + t) * 32 + pj];
            float hp = hbuf[par * 256 + ps * 128 + cbase + pj];
            float ct;
            if (wc) { float ec = expf(i_); ct = (ec * g2 + ewca[ps * 32 + pj]) / (ec + ewa[ps * 32 + pj]); }
            else    ct = f_ * cp + i_ * g2;
            float ht = o_ * tanhf(ct);
            int LB = ps ? Lb1 : Lb0;
            bool v = dir ? (t >= 128 - LB) : (t < LB);
            float hn = v ? ht : hp;
            float cn = v ? ct : cp;
            int hoff = (par ^ 1) * 256 + ps * 128 + cbase + pj;
            unsigned la = smem_u32(&hbuf[hoff]);
            hbuf[hoff] = hn;
            #pragma unroll
            for (int p = 0; p < 4; ++p) if (p != rank) st_peer_f32(la, p, hn);
            ch[(ps * 129 + t + 1) * 32 + pj] = cn;
            g_hh[sid0 + ps][(t + 1) * 128 + cbase + pj] = hn;
            int pos = dir ? 127 - t : t;
            g_feats[((size_t)(b0 + ps) * 128 + pos) * 256 + dir * 128 + cbase + pj] = v ? ht : 0.f;
            __syncwarp();
            if ((tid & 31) == 0) {
                mbar_arrive_self(bha);
                #pragma unroll
                for (int p = 0; p < 4; ++p) if (p != rank) mbar_arrive_peer(bha, p);
            }
        }
        mbar_wait(bha, (unsigned)((t >> 1) & 1));
    }
    cluster_sync_();
}

// ---------------- dense projection ----------------
__global__ void dense_kernel(const float* __restrict__ W, const float* __restrict__ bias)
{
    __shared__ float Wsm[8192];
    __shared__ float Fs[16 * 256];
    int tid = threadIdx.x;
    int row0 = blockIdx.x * 16;
    for (int i = tid; i < 8192; i += 256) Wsm[i] = W[i];
    for (int i = tid; i < 4096; i += 256) Fs[i] = g_feats[(size_t)row0 * 256 + i];
    __syncthreads();
    int l = tid & 31, rr = tid >> 5;
    float a0 = bias[l], a1 = a0;
    const float* f0 = Fs + rr * 256;
    const float* f1 = Fs + (rr + 8) * 256;
    #pragma unroll 8
    for (int q = 0; q < 256; ++q) {
        float w = Wsm[q * 32 + l];
        a0 = fmaf(f0[q], w, a0);
        a1 = fmaf(f1[q], w, a1);
    }
    g_logits[(size_t)(row0 + rr) * 32 + l]     = a0;
    g_logits[(size_t)(row0 + rr + 8) * 32 + l] = a1;
}

// ---------------- CRF ----------------
__global__ void crf_kernel(const int* __restrict__ label, const int* __restrict__ seq_len,
                           const float* __restrict__ crf_T)
{
    int b = blockIdx.x, l = threadIdx.x;
    __shared__ float Ts[1024], Es[1024];
    for (int i = l; i < 1024; i += 32) { float v = crf_T[i]; Ts[i] = v; Es[i] = expf(v); }
    __syncwarp();
    int L = seq_len[b];
    const float* lg = g_logits + (size_t)b * 4096;
    float alpha = lg[l];
    for (int t = 1; t < 128; ++t) {
        float m = alpha;
        for (int o = 16; o; o >>= 1) m = fmaxf(m, __shfl_xor_sync(0xffffffffu, m, o));
        float a = expf(alpha - m);
        float S = 0.f;
        #pragma unroll
        for (int i = 0; i < 32; ++i) {
            float ai = __shfl_sync(0xffffffffu, a, i);
            S = fmaf(ai, Es[i * 32 + l], S);
        }
        float nv = m + logf(S) + lg[t * 32 + l];
        if (t < L) alpha = nv;
    }
    float m = alpha;
    for (int o = 16; o; o >>= 1) m = fmaxf(m, __shfl_xor_sync(0xffffffffu, m, o));
    float e = expf(alpha - m);
    for (int o = 16; o; o >>= 1) e += __shfl_xor_sync(0xffffffffu, e, o);
    float logZ = m + logf(e);
    float gsum = 0.f;
    for (int t = l; t < 128; t += 32) {
        if (t < L) {
            int lab = label[b * 128 + t];
            gsum += lg[t * 32 + lab];
            if (t >= 1) gsum += Ts[label[b * 128 + t - 1] * 32 + lab];
        }
    }
    for (int o = 16; o; o >>= 1) gsum += __shfl_xor_sync(0xffffffffu, gsum, o);
    if (l == 0) g_res[b] = logZ - gsum;
}

__global__ void finalize_kernel(float* out)
{
    float s = 0.f;
    #pragma unroll
    for (int b = 0; b < 16; ++b) s += g_res[b];
    out[0] = s * 0.0625f;
}

// ---------------- launch ----------------
extern "C" void kernel_launch(void* const* d_in, const int* in_sizes, int n_in,
                              void* d_out, int out_size)
{
    const int*   char_ids    = (const int*)d_in[0];
    const int*   kb_word_ids = (const int*)d_in[1];
    const int*   word_begin  = (const int*)d_in[2];
    const int*   word_len    = (const int*)d_in[3];
    const int*   label       = (const int*)d_in[4];
    const int*   seq_len     = (const int*)d_in[5];
    const float* char_emb    = (const float*)d_in[6];
    const float* kb_emb      = (const float*)d_in[7];
    const float* dense_W     = (const float*)d_in[8];
    const float* dense_b     = (const float*)d_in[9];
    const float* crf_T       = (const float*)d_in[10];
    const float* f_Wcx = (const float*)d_in[11];
    const float* f_Wch = (const float*)d_in[12];
    const float* f_bc  = (const float*)d_in[13];
    const float* f_Wwx = (const float*)d_in[14];
    const float* f_Wwh = (const float*)d_in[15];
    const float* f_bw  = (const float*)d_in[16];
    const float* f_Wlx = (const float*)d_in[17];
    const float* f_Wlc = (const float*)d_in[18];
    const float* f_bl  = (const float*)d_in[19];
    const float* r_Wcx = (const float*)d_in[20];
    const float* r_Wch = (const float*)d_in[21];
    const float* r_bc  = (const float*)d_in[22];
    const float* r_Wwx = (const float*)d_in[23];
    const float* r_Wwh = (const float*)d_in[24];
    const float* r_bw  = (const float*)d_in[25];
    const float* r_Wlx = (const float*)d_in[26];
    const float* r_Wlc = (const float*)d_in[27];
    const float* r_bl  = (const float*)d_in[28];

    const int LAT_SMEM = LAT_FLOATS * 4;  // 172800 B
    cudaFuncSetAttribute(lattice_kernel, cudaFuncAttributeMaxDynamicSharedMemorySize, LAT_SMEM);

    gemm_gather_kernel<<<dim3(8, 64), 256>>>(0, char_ids, kb_word_ids, char_emb, kb_emb,
                                             f_Wcx, r_Wcx, f_bc, r_bc, 512, 2048);
    gemm_gather_kernel<<<dim3(2, 64), 256>>>(1, char_ids, kb_word_ids, char_emb, kb_emb,
                                             f_Wlx, r_Wlx, f_bl, r_bl, 128, 2048);
    gemm_gather_kernel<<<dim3(6, 32), 256>>>(2, char_ids, kb_word_ids, char_emb, kb_emb,
                                             f_Wwx, r_Wwx, f_bw, r_bw, 384, 1024);

    lattice_kernel<<<64, 256, LAT_SMEM>>>(word_begin, word_len, seq_len,
                                          f_Wch, f_Wwh, f_Wlc, r_Wch, r_Wwh, r_Wlc);

    dense_kernel<<<128, 256>>>(dense_W, dense_b);
    crf_kernel<<<16, 32>>>(label, seq_len, crf_T);
    finalize_kernel<<<1, 1>>>((float*)d_out);
}